// round 5
// baseline (speedup 1.0000x reference)
#include <cuda_runtime.h>
#include <cstdint>

#define H       64
#define INP     32
#define NF      96
#define TT      128
#define BM      56      // batch elements per CTA
#define BMP     60      // padded row width (floats)
#define NTHR    448     // 64 units * 7 groups
#define BPT     8       // batch elements per thread (4 packed pairs)

typedef unsigned long long ull;

// shared memory layout (floats)
#define OFF_W4    0                         // [96][64] float4 : {wi,wf,wg,wo}; rows 0..31 = W_ih, 32..95 = W_hh
#define OFF_B4    (OFF_W4 + NF*H*4)         // [64] float4
#define OFF_XS    (OFF_B4 + H*4)            // [2][32][BMP]
#define OFF_HS    (OFF_XS + 2*INP*BMP)      // [2][64][BMP]
#define SMEM_FLOATS (OFF_HS + 2*H*BMP)
#define SMEM_BYTES  (SMEM_FLOATS * 4)

__device__ __forceinline__ ull bcast2(float w) {
    ull r; asm("mov.b64 %0, {%1, %1};" : "=l"(r) : "f"(w)); return r;
}
__device__ __forceinline__ void unpack2(ull v, float& lo, float& hi) {
    asm("mov.b64 {%0, %1}, %2;" : "=f"(lo), "=f"(hi) : "l"(v));
}
__device__ __forceinline__ void fma2(ull& d, ull a, ull b) {
    asm("fma.rn.f32x2 %0, %1, %2, %0;" : "+l"(d) : "l"(a), "l"(b));
}

__device__ __forceinline__ float fsig(float v) {
    return __fdividef(1.0f, 1.0f + __expf(-v));
}
__device__ __forceinline__ float ftanh(float v) {
    float a = fabsf(v);
    float e = __expf(-2.0f * a);
    float r = __fdividef(1.0f - e, 1.0f + e);
    return copysignf(r, v);
}

// accumulate N features: wbase = w4 + row0*256 + k*4 ; sbase = state + b0
template<int N>
__device__ __forceinline__ void accum(const float* __restrict__ wbase,
                                      const float* __restrict__ sbase,
                                      ull a0[4], ull a1[4], ull a2[4], ull a3[4])
{
#pragma unroll 4
    for (int j = 0; j < N; ++j) {
        float4 w = *(const float4*)(wbase + j * 256);
        ull wi = bcast2(w.x), wf = bcast2(w.y),
            wg = bcast2(w.z), wo = bcast2(w.w);
        ulonglong2 va = *(const ulonglong2*)(sbase + j * BMP);
        ulonglong2 vb = *(const ulonglong2*)(sbase + j * BMP + 4);
        ull pr[4] = {va.x, va.y, vb.x, vb.y};
#pragma unroll
        for (int q = 0; q < 4; ++q) {
            fma2(a0[q], wi, pr[q]);
            fma2(a1[q], wf, pr[q]);
            fma2(a2[q], wg, pr[q]);
            fma2(a3[q], wo, pr[q]);
        }
    }
}

__global__ void __launch_bounds__(NTHR, 1)
lstm_kernel(const float* __restrict__ x,
            const float* __restrict__ W_ih,
            const float* __restrict__ W_hh,
            const float* __restrict__ b_ih,
            const float* __restrict__ b_hh,
            const float* __restrict__ W_fc,
            const float* __restrict__ b_fc,
            float* __restrict__ out,
            int Btotal)
{
    extern __shared__ float sm[];
    float* w4 = sm + OFF_W4;
    float* b4 = sm + OFF_B4;
    float* xs = sm + OFF_XS;   // xs[buf*INP*BMP + j*BMP + b]
    float* hs = sm + OFF_HS;   // hs[buf*H*BMP   + j*BMP + b]

    const int tid   = threadIdx.x;
    const int bbase = blockIdx.x * BM;
    const int k     = tid & 63;
    const int grp   = tid >> 6;
    const int b0    = grp * BPT;

    // ---- stage weights into packed-gate layout (one-time) ----
    for (int n = tid; n < NF * 256; n += NTHR) {
        int j = n >> 8, g = n & 255;
        float v = (j < INP) ? W_ih[g * INP + j] : W_hh[g * H + (j - INP)];
        int kk = g & 63, gate = g >> 6;
        w4[(j * H + kk) * 4 + gate] = v;
    }
    for (int n = tid; n < 256; n += NTHR) {
        int kk = n & 63, gate = n >> 6;
        b4[kk * 4 + gate] = b_ih[gate * H + kk] + b_hh[gate * H + kk];
    }
    for (int n = tid; n < 2 * H * BMP; n += NTHR)
        hs[n] = 0.0f;

    // ---- x staging: each thread owns one float4 per step ----
    const int lb = tid >> 3;                 // 0..55 batch within tile
    const int iv = (tid & 7) * 4;            // input feature base
    const bool bvalid = (bbase + lb) < Btotal;
    // clamped (branch-free) source pointer: invalid batches read batch 0 (discarded)
    const float* xrowS = x + (bvalid ? ((size_t)(bbase + lb) * TT * INP) : 0) + iv;

    // stage x(0) -> xb0, x(1) -> xb1, prefetch x(2)
    {
        float4 x0 = *(const float4*)(xrowS);
        float4 x1 = *(const float4*)(xrowS + INP);
        float* xb0 = xs;
        float* xb1 = xs + INP * BMP;
        xb0[(iv + 0) * BMP + lb] = x0.x;  xb0[(iv + 1) * BMP + lb] = x0.y;
        xb0[(iv + 2) * BMP + lb] = x0.z;  xb0[(iv + 3) * BMP + lb] = x0.w;
        xb1[(iv + 0) * BMP + lb] = x1.x;  xb1[(iv + 1) * BMP + lb] = x1.y;
        xb1[(iv + 2) * BMP + lb] = x1.z;  xb1[(iv + 3) * BMP + lb] = x1.w;
    }
    float4 xr = *(const float4*)(xrowS + 2 * INP);   // x(2)
    __syncthreads();

    float c[BPT];
#pragma unroll
    for (int b = 0; b < BPT; ++b) c[b] = 0.0f;

    const float4 bk = *(const float4*)&b4[k * 4];
    const ull bb0 = bcast2(bk.x), bb1 = bcast2(bk.y),
              bb2 = bcast2(bk.z), bb3 = bcast2(bk.w);

    const float* w4k  = w4 + k * 4;            // feature rows (x part, rows 0..31)
    const float* w4kh = w4 + 32 * 256 + k * 4; // h part (rows 32..95)

    // acc set A: gates for even step (already bias + Wx.x(t)); set B: odd step
    ull A0[4], A1[4], A2[4], A3[4], B0[4], B1[4], B2[4], B3[4];
#pragma unroll
    for (int q = 0; q < 4; ++q) { A0[q]=bb0; A1[q]=bb1; A2[q]=bb2; A3[q]=bb3; }
    accum<INP>(w4k, xs + b0, A0, A1, A2, A3);   // + Wx . x(0)

#define ACTIVATE(a0,a1,a2,a3,HN)                                          \
    {                                                                     \
        float* hn = (HN);                                                 \
        _Pragma("unroll")                                                 \
        for (int q = 0; q < 4; ++q) {                                     \
            float i0,i1,f0,f1,g0,g1,o0,o1;                                \
            unpack2(a0[q], i0, i1); unpack2(a1[q], f0, f1);               \
            unpack2(a2[q], g0, g1); unpack2(a3[q], o0, o1);               \
            float ig=fsig(i0), fg=fsig(f0), gg=ftanh(g0), og=fsig(o0);    \
            float cn = fmaf(fg, c[2*q], ig*gg);                           \
            c[2*q] = cn;                                                  \
            float hv0 = og * ftanh(cn);                                   \
            ig=fsig(i1); fg=fsig(f1); gg=ftanh(g1); og=fsig(o1);          \
            cn = fmaf(fg, c[2*q+1], ig*gg);                               \
            c[2*q+1] = cn;                                                \
            float hv1 = og * ftanh(cn);                                   \
            *(float2*)&hn[2*q] = make_float2(hv0, hv1);                   \
        }                                                                 \
    }

#define STAGE_X(XBW, T)                                                   \
    {                                                                     \
        float* xw = (XBW);                                                \
        xw[(iv+0)*BMP+lb]=xr.x; xw[(iv+1)*BMP+lb]=xr.y;                   \
        xw[(iv+2)*BMP+lb]=xr.z; xw[(iv+3)*BMP+lb]=xr.w;                   \
        int tn = (T) + 3; if (tn > TT-1) tn = TT-1;                       \
        xr = *(const float4*)(xrowS + (size_t)tn * INP);                  \
    }

    float* const hb0 = hs;
    float* const hb1 = hs + H * BMP;
    float* const xb0 = xs;
    float* const xb1 = xs + INP * BMP;

    for (int t = 0; t < TT; t += 2) {
        // ---- substep even t: h(t-1) in hb0 -> h(t) to hb1; x(t+1) in xb1 ----
        accum<H>(w4kh, hb0 + b0, A0, A1, A2, A3);          // + Wh . h(t-1)
#pragma unroll
        for (int q = 0; q < 4; ++q) { B0[q]=bb0; B1[q]=bb1; B2[q]=bb2; B3[q]=bb3; }
        accum<INP>(w4k, xb1 + b0, B0, B1, B2, B3);         // next-step x-part (independent)
        ACTIVATE(A0, A1, A2, A3, hb1 + k * BMP + b0);      // MUFU overlaps accum above
        STAGE_X(xb0, t);                                   // x(t+2) -> xb0, prefetch x(t+3)
        __syncthreads();

        // ---- substep odd t+1: h(t) in hb1 -> h(t+1) to hb0; x(t+2) in xb0 ----
        accum<H>(w4kh, hb1 + b0, B0, B1, B2, B3);
#pragma unroll
        for (int q = 0; q < 4; ++q) { A0[q]=bb0; A1[q]=bb1; A2[q]=bb2; A3[q]=bb3; }
        accum<INP>(w4k, xb0 + b0, A0, A1, A2, A3);
        ACTIVATE(B0, B1, B2, B3, hb0 + k * BMP + b0);
        STAGE_X(xb1, t + 1);
        __syncthreads();
    }

    // ---- final FC: h(127) lives in hb0 ----
    const int ob = tid >> 3;
    const int oo = tid & 7;
    if (ob < BM && (bbase + ob) < Btotal) {
        float a = b_fc[oo];
#pragma unroll 8
        for (int kk = 0; kk < H; ++kk)
            a = fmaf(hb0[kk * BMP + ob], W_fc[oo * H + kk], a);
        out[(size_t)(bbase + ob) * 8 + oo] = a;
    }
}

extern "C" void kernel_launch(void* const* d_in, const int* in_sizes, int n_in,
                              void* d_out, int out_size) {
    const float* x    = (const float*)d_in[0];
    const float* W_ih = (const float*)d_in[1];
    const float* W_hh = (const float*)d_in[2];
    const float* b_ih = (const float*)d_in[3];
    const float* b_hh = (const float*)d_in[4];
    const float* W_fc = (const float*)d_in[5];
    const float* b_fc = (const float*)d_in[6];
    float* out = (float*)d_out;

    const int B = in_sizes[0] / (TT * INP);   // 8192
    const int grid = (B + BM - 1) / BM;       // 147

    cudaFuncSetAttribute(lstm_kernel,
                         cudaFuncAttributeMaxDynamicSharedMemorySize,
                         SMEM_BYTES);
    lstm_kernel<<<grid, NTHR, SMEM_BYTES>>>(x, W_ih, W_hh, b_ih, b_hh,
                                            W_fc, b_fc, out, B);
}

// round 7
// speedup vs baseline: 2.5019x; 2.5019x over previous
#include <cuda_runtime.h>
#include <cstdint>

#define TT    128
#define BM    56          // valid batches per CTA (padded to 64 in the GEMM)
#define NTHR  512
#define PS    100         // state pitch (floats): rows=batch(64), cols=feat(96)+pad
#define PG    74          // gates scratch pitch (floats): rows=gate(256), cols=batch(64)

#define STATE_F   0
#define SCR_F     (64*PS)                 // 6400
#define BIAS_F    (SCR_F + 256*PG)        // 25344
#define SMEM_FLOATS (BIAS_F + 256)        // 25600
#define SMEM_BYTES  (SMEM_FLOATS*4)       // 102400

__device__ __forceinline__ uint32_t f2tf(float f) {
    uint32_t r; asm("cvt.rna.tf32.f32 %0, %1;" : "=r"(r) : "f"(f)); return r;
}
__device__ __forceinline__ float tf2f(uint32_t u) { return __uint_as_float(u); }

__device__ __forceinline__ void mma8(float d[4], const uint32_t a[4],
                                     uint32_t b0, uint32_t b1) {
    asm volatile(
        "mma.sync.aligned.m16n8k8.row.col.f32.tf32.tf32.f32 "
        "{%0,%1,%2,%3}, {%4,%5,%6,%7}, {%8,%9}, {%0,%1,%2,%3};"
        : "+f"(d[0]), "+f"(d[1]), "+f"(d[2]), "+f"(d[3])
        : "r"(a[0]), "r"(a[1]), "r"(a[2]), "r"(a[3]), "r"(b0), "r"(b1));
}

__device__ __forceinline__ float fsig(float v) {
    return __fdividef(1.0f, 1.0f + __expf(-v));
}
__device__ __forceinline__ float ftanh(float v) {
    float a = fabsf(v);
    float e = __expf(-2.0f * a);
    float r = __fdividef(1.0f - e, 1.0f + e);
    return copysignf(r, v);
}

// weight element for GEMM A[row=unit*4+gate][k]  (k<32: W_ih, else W_hh)
__device__ __forceinline__ float wval(const float* __restrict__ W_ih,
                                      const float* __restrict__ W_hh,
                                      int row, int k) {
    int u = row >> 2, g = row & 3;
    return (k < 32) ? W_ih[(g * 64 + u) * 32 + k]
                    : W_hh[(g * 64 + u) * 64 + (k - 32)];
}

__global__ void __launch_bounds__(NTHR, 1)
lstm_mma(const float* __restrict__ x,
         const float* __restrict__ W_ih,
         const float* __restrict__ W_hh,
         const float* __restrict__ b_ih,
         const float* __restrict__ b_hh,
         const float* __restrict__ W_fc,
         const float* __restrict__ b_fc,
         float* __restrict__ out,
         int Btotal)
{
    extern __shared__ float sm[];
    float* state = sm + STATE_F;   // state[batch][feat]: 0-31 x(t) tf32, 32-95 h(t-1) tf32
    float* scr   = sm + SCR_F;     // scr[gate_row][batch]
    float* bias  = sm + BIAS_F;    // bias[unit*4+gate]

    const int tid   = threadIdx.x;
    const int w     = tid >> 5;
    const int l     = tid & 31;
    const int bbase = blockIdx.x * BM;

    // ---- one-time: bias + zero state ----
    for (int m = tid; m < 256; m += NTHR) {     // m = gate*64+unit
        int u = m & 63, g = m >> 6;
        bias[u * 4 + g] = b_ih[m] + b_hh[m];
    }
    for (int i = tid; i < 64 * PS; i += NTHR)
        state[i] = 0.0f;

    // ---- persistent A fragments: warp w owns gate rows 16w..16w+15, K=96 (12 k-tiles) ----
    uint32_t A[12][4];
    {
        const int r0 = 16 * w + (l >> 2);
#pragma unroll
        for (int kt = 0; kt < 12; ++kt) {
            const int k0 = kt * 8 + (l & 3);
            A[kt][0] = f2tf(wval(W_ih, W_hh, r0,     k0));
            A[kt][1] = f2tf(wval(W_ih, W_hh, r0 + 8, k0));
            A[kt][2] = f2tf(wval(W_ih, W_hh, r0,     k0 + 4));
            A[kt][3] = f2tf(wval(W_ih, W_hh, r0 + 8, k0 + 4));
        }
    }

    // ---- x staging (448 threads): batch lb, features iv..iv+3 ----
    const int lb  = tid >> 3;
    const int iv  = (tid & 7) * 4;
    const bool xth  = (tid < 448);
    const bool bval = xth && (bbase + lb) < Btotal;
    const float* xrow = x + (bval ? (size_t)(bbase + lb) * TT * 32 : 0) + iv;

    float4 xr;
    if (xth) {
        float4 x0 = *(const float4*)xrow;
        float4 s;
        s.x = tf2f(f2tf(x0.x)); s.y = tf2f(f2tf(x0.y));
        s.z = tf2f(f2tf(x0.z)); s.w = tf2f(f2tf(x0.w));
        *(float4*)&state[lb * PS + iv] = s;
        xr = *(const float4*)(xrow + 32);
    }
    __syncthreads();

    // ---- activation mapping: thread = (unit au, 7 batches ab..ab+6) ----
    const int au = tid >> 3;            // 0..63
    const int ab = (tid & 7) * 7;       // 0..49
    const float4 bz = *(const float4*)&bias[au * 4];
    float cst[7];
#pragma unroll
    for (int i = 0; i < 7; ++i) cst[i] = 0.0f;

    const int fr = l >> 2;              // fragment row group 0..7
    const int fc = l & 3;               // fragment col group 0..3

    for (int t = 0; t < TT; ++t) {
        // ===== GEMM phase: D[16 rows of warp w][64 batch] =====
#pragma unroll
        for (int ntp = 0; ntp < 4; ++ntp) {
            const int n0 = ntp * 16;            // two n8 tiles: n0, n0+8
            float d0[4] = {0.f, 0.f, 0.f, 0.f};
            float d1[4] = {0.f, 0.f, 0.f, 0.f};
#pragma unroll
            for (int kt = 0; kt < 12; ++kt) {
                const float* sp = state + kt * 8 + fc;
                uint32_t b00 = __float_as_uint(sp[(n0 + fr) * PS]);
                uint32_t b01 = __float_as_uint(sp[(n0 + fr) * PS + 4]);
                uint32_t b10 = __float_as_uint(sp[(n0 + 8 + fr) * PS]);
                uint32_t b11 = __float_as_uint(sp[(n0 + 8 + fr) * PS + 4]);
                mma8(d0, A[kt], b00, b01);
                mma8(d1, A[kt], b10, b11);
            }
            // store D to scratch: rows 16w+fr(+8), cols n + 2*fc(+1)
            const int r0 = 16 * w + fr;
            const int c0 = n0 + 2 * fc;
            *(float2*)&scr[r0 * PG + c0]           = make_float2(d0[0], d0[1]);
            *(float2*)&scr[(r0 + 8) * PG + c0]     = make_float2(d0[2], d0[3]);
            *(float2*)&scr[r0 * PG + c0 + 8]       = make_float2(d1[0], d1[1]);
            *(float2*)&scr[(r0 + 8) * PG + c0 + 8] = make_float2(d1[2], d1[3]);
        }
        __syncthreads();

        // ===== activation phase =====
        const bool lastt = (t == TT - 1);
        const float* g0 = scr + (au * 4 + 0) * PG + ab;
        const float* g1 = scr + (au * 4 + 1) * PG + ab;
        const float* g2 = scr + (au * 4 + 2) * PG + ab;
        const float* g3 = scr + (au * 4 + 3) * PG + ab;
#pragma unroll
        for (int i = 0; i < 7; ++i) {
            float gi = fsig(g0[i] + bz.x);
            float gf = fsig(g1[i] + bz.y);
            float gg = ftanh(g2[i] + bz.z);
            float go = fsig(g3[i] + bz.w);
            float cn = fmaf(gf, cst[i], gi * gg);
            cst[i] = cn;
            float h = go * ftanh(cn);
            state[(ab + i) * PS + 32 + au] = lastt ? h : tf2f(f2tf(h));
        }

        // stage x(t+1)
        if (xth && t + 1 < TT) {
            float4 s;
            s.x = tf2f(f2tf(xr.x)); s.y = tf2f(f2tf(xr.y));
            s.z = tf2f(f2tf(xr.z)); s.w = tf2f(f2tf(xr.w));
            *(float4*)&state[lb * PS + iv] = s;
            int tn = (t + 2 < TT) ? (t + 2) : (TT - 1);
            xr = *(const float4*)(xrow + (size_t)tn * 32);
        }
        __syncthreads();
    }

    // ---- final FC: h(T) raw f32 in state[b][32..95] ----
    if (xth) {
        const int ob = tid >> 3, oo = tid & 7;
        if ((bbase + ob) < Btotal) {
            const float* hv = state + ob * PS + 32;
            float a = b_fc[oo];
#pragma unroll 8
            for (int k = 0; k < 64; ++k)
                a = fmaf(hv[k], W_fc[oo * 64 + k], a);
            out[(size_t)(bbase + ob) * 8 + oo] = a;
        }
    }
}

extern "C" void kernel_launch(void* const* d_in, const int* in_sizes, int n_in,
                              void* d_out, int out_size) {
    const float* x    = (const float*)d_in[0];
    const float* W_ih = (const float*)d_in[1];
    const float* W_hh = (const float*)d_in[2];
    const float* b_ih = (const float*)d_in[3];
    const float* b_hh = (const float*)d_in[4];
    const float* W_fc = (const float*)d_in[5];
    const float* b_fc = (const float*)d_in[6];
    float* out = (float*)d_out;

    const int B = in_sizes[0] / (TT * 32);    // 8192
    const int grid = (B + BM - 1) / BM;       // 147

    cudaFuncSetAttribute(lstm_mma,
                         cudaFuncAttributeMaxDynamicSharedMemorySize,
                         SMEM_BYTES);
    lstm_mma<<<grid, NTHR, SMEM_BYTES>>>(x, W_ih, W_hh, b_ih, b_hh,
                                         W_fc, b_fc, out, B);
}

// round 8
// speedup vs baseline: 3.3715x; 1.3475x over previous
#include <cuda_runtime.h>
#include <cuda_fp16.h>
#include <cstdint>

#define TT    128
#define BM    56
#define NTHR  512
#define PW    52          // 32-bit words per state row (104 halves: k 0..95 + pad)
#define PG    74          // gates scratch pitch (floats)
#define PH    65          // final-h pitch (floats)

#define SCR_F     3328                  // after 64*PW state words
#define BIAS_F    (SCR_F + 256*PG)      // 22272
#define HFIN_F    (BIAS_F + 256)        // 22528
#define SMEM_FLOATS (HFIN_F + 64*PH)    // 26688
#define SMEM_BYTES  (SMEM_FLOATS*4)     // 106752

__device__ __forceinline__ uint32_t packh2(float lo, float hi) {
    __half2 p = __halves2half2(__float2half_rn(lo), __float2half_rn(hi));
    return *reinterpret_cast<uint32_t*>(&p);
}

__device__ __forceinline__ void mma16(float d[4], const uint32_t a[4],
                                      uint32_t b0, uint32_t b1) {
    asm volatile(
        "mma.sync.aligned.m16n8k16.row.col.f32.f16.f16.f32 "
        "{%0,%1,%2,%3}, {%4,%5,%6,%7}, {%8,%9}, {%0,%1,%2,%3};"
        : "+f"(d[0]), "+f"(d[1]), "+f"(d[2]), "+f"(d[3])
        : "r"(a[0]), "r"(a[1]), "r"(a[2]), "r"(a[3]), "r"(b0), "r"(b1));
}

__device__ __forceinline__ float fsig(float v) {
    return __fdividef(1.0f, 1.0f + __expf(-v));
}
__device__ __forceinline__ float ftanh(float v) {
    float a = fabsf(v);
    float e = __expf(-2.0f * a);
    float r = __fdividef(1.0f - e, 1.0f + e);
    return copysignf(r, v);
}

// GEMM A element: A[row=unit*4+gate][k]  (k<32: W_ih, else W_hh)
__device__ __forceinline__ float wval(const float* __restrict__ W_ih,
                                      const float* __restrict__ W_hh,
                                      int row, int k) {
    int u = row >> 2, g = row & 3;
    return (k < 32) ? W_ih[(g * 64 + u) * 32 + k]
                    : W_hh[(g * 64 + u) * 64 + (k - 32)];
}

__global__ void __launch_bounds__(NTHR, 1)
lstm_mma(const float* __restrict__ x,
         const float* __restrict__ W_ih,
         const float* __restrict__ W_hh,
         const float* __restrict__ b_ih,
         const float* __restrict__ b_hh,
         const float* __restrict__ W_fc,
         const float* __restrict__ b_fc,
         float* __restrict__ out,
         int Btotal)
{
    extern __shared__ float sm[];
    uint32_t* stw  = (uint32_t*)sm;      // state[batch][k-pair words]: k 0-31 x fp16, 32-95 h fp16
    __half*   sth  = (__half*)sm;        // half-granular view of state
    float* scr  = sm + SCR_F;            // scr[gate_row][batch] f32
    float* bias = sm + BIAS_F;           // bias[unit*4+gate]
    float* hfin = sm + HFIN_F;           // hfin[batch][unit] raw f32 h(T)

    const int tid   = threadIdx.x;
    const int w     = tid >> 5;
    const int l     = tid & 31;
    const int bbase = blockIdx.x * BM;

    // ---- one-time init ----
    for (int m = tid; m < 256; m += NTHR) {     // m = gate*64+unit
        int u = m & 63, g = m >> 6;
        bias[u * 4 + g] = b_ih[m] + b_hh[m];
    }
    for (int i = tid; i < 64 * PW; i += NTHR)
        stw[i] = 0u;

    // ---- persistent fp16 A fragments: warp w owns gate rows 16w..16w+15, 6 k16-tiles ----
    uint32_t A[6][4];
    {
        const int r0 = 16 * w + (l >> 2);
#pragma unroll
        for (int kt = 0; kt < 6; ++kt) {
            const int k0 = kt * 16 + (l & 3) * 2;
            A[kt][0] = packh2(wval(W_ih, W_hh, r0,     k0),     wval(W_ih, W_hh, r0,     k0 + 1));
            A[kt][1] = packh2(wval(W_ih, W_hh, r0 + 8, k0),     wval(W_ih, W_hh, r0 + 8, k0 + 1));
            A[kt][2] = packh2(wval(W_ih, W_hh, r0,     k0 + 8), wval(W_ih, W_hh, r0,     k0 + 9));
            A[kt][3] = packh2(wval(W_ih, W_hh, r0 + 8, k0 + 8), wval(W_ih, W_hh, r0 + 8, k0 + 9));
        }
    }

    // ---- x staging (448 threads): batch lb, features iv..iv+3 -> 2 packed words ----
    const int lb  = tid >> 3;
    const int iv  = (tid & 7) * 4;
    const bool xth  = (tid < 448);
    const bool bval = xth && (bbase + lb) < Btotal;
    const float* xrow = x + (bval ? (size_t)(bbase + lb) * TT * 32 : 0) + iv;

    float4 xr;
    if (xth) {
        float4 x0 = *(const float4*)xrow;
        stw[lb * PW + (iv >> 1)]     = packh2(x0.x, x0.y);
        stw[lb * PW + (iv >> 1) + 1] = packh2(x0.z, x0.w);
        xr = *(const float4*)(xrow + 32);
    }
    __syncthreads();

    // ---- activation mapping: thread = (unit au, 7 batches ab..ab+6) ----
    const int au = tid >> 3;            // 0..63
    const int ab = (tid & 7) * 7;       // 0..49
    const float4 bz = *(const float4*)&bias[au * 4];
    float cst[7];
#pragma unroll
    for (int i = 0; i < 7; ++i) cst[i] = 0.0f;

    const int fr = l >> 2;              // fragment group 0..7
    const int fc = l & 3;               // fragment sub 0..3

    for (int t = 0; t < TT; ++t) {
        // ===== GEMM: D[16 gate rows of warp w][64 batch] =====
#pragma unroll
        for (int ntp = 0; ntp < 4; ++ntp) {
            const int n0 = ntp * 16;
            float d0[4] = {0.f, 0.f, 0.f, 0.f};
            float d1[4] = {0.f, 0.f, 0.f, 0.f};
            const uint32_t* s0 = stw + (n0 + fr) * PW + fc;
            const uint32_t* s1 = stw + (n0 + 8 + fr) * PW + fc;
#pragma unroll
            for (int kt = 0; kt < 6; ++kt) {
                uint32_t b00 = s0[kt * 8];
                uint32_t b01 = s0[kt * 8 + 4];
                uint32_t b10 = s1[kt * 8];
                uint32_t b11 = s1[kt * 8 + 4];
                mma16(d0, A[kt], b00, b01);
                mma16(d1, A[kt], b10, b11);
            }
            const int r0 = 16 * w + fr;
            const int c0 = n0 + 2 * fc;
            *(float2*)&scr[r0 * PG + c0]           = make_float2(d0[0], d0[1]);
            *(float2*)&scr[(r0 + 8) * PG + c0]     = make_float2(d0[2], d0[3]);
            *(float2*)&scr[r0 * PG + c0 + 8]       = make_float2(d1[0], d1[1]);
            *(float2*)&scr[(r0 + 8) * PG + c0 + 8] = make_float2(d1[2], d1[3]);
        }
        __syncthreads();

        // ===== activations =====
        const bool lastt = (t == TT - 1);
        const float* g0 = scr + (au * 4 + 0) * PG + ab;
        const float* g1 = scr + (au * 4 + 1) * PG + ab;
        const float* g2 = scr + (au * 4 + 2) * PG + ab;
        const float* g3 = scr + (au * 4 + 3) * PG + ab;
#pragma unroll
        for (int i = 0; i < 7; ++i) {
            float gi = fsig(g0[i] + bz.x);
            float gf = fsig(g1[i] + bz.y);
            float gg = ftanh(g2[i] + bz.z);
            float go = fsig(g3[i] + bz.w);
            float cn = fmaf(gf, cst[i], gi * gg);
            cst[i] = cn;
            float h = go * ftanh(cn);
            if (lastt) hfin[(ab + i) * PH + au] = h;
            else       sth[(ab + i) * (2 * PW) + 32 + au] = __float2half_rn(h);
        }

        // stage x(t+1)
        if (xth && t + 1 < TT) {
            stw[lb * PW + (iv >> 1)]     = packh2(xr.x, xr.y);
            stw[lb * PW + (iv >> 1) + 1] = packh2(xr.z, xr.w);
            int tn = (t + 2 < TT) ? (t + 2) : (TT - 1);
            xr = *(const float4*)(xrow + (size_t)tn * 32);
        }
        __syncthreads();
    }

    // ---- final FC on raw f32 h(T) ----
    if (xth) {
        const int ob = tid >> 3, oo = tid & 7;
        if ((bbase + ob) < Btotal) {
            const float* hv = hfin + ob * PH;
            float a = b_fc[oo];
#pragma unroll 8
            for (int k = 0; k < 64; ++k)
                a = fmaf(hv[k], W_fc[oo * 64 + k], a);
            out[(size_t)(bbase + ob) * 8 + oo] = a;
        }
    }
}

extern "C" void kernel_launch(void* const* d_in, const int* in_sizes, int n_in,
                              void* d_out, int out_size) {
    const float* x    = (const float*)d_in[0];
    const float* W_ih = (const float*)d_in[1];
    const float* W_hh = (const float*)d_in[2];
    const float* b_ih = (const float*)d_in[3];
    const float* b_hh = (const float*)d_in[4];
    const float* W_fc = (const float*)d_in[5];
    const float* b_fc = (const float*)d_in[6];
    float* out = (float*)d_out;

    const int B = in_sizes[0] / (TT * 32);    // 8192
    const int grid = (B + BM - 1) / BM;       // 147

    cudaFuncSetAttribute(lstm_mma,
                         cudaFuncAttributeMaxDynamicSharedMemorySize,
                         SMEM_BYTES);
    lstm_mma<<<grid, NTHR, SMEM_BYTES>>>(x, W_ih, W_hh, b_ih, b_hh,
                                         W_fc, b_fc, out, B);
}

// round 9
// speedup vs baseline: 4.9972x; 1.4822x over previous
#include <cuda_runtime.h>
#include <cuda_fp16.h>
#include <cstdint>

#define TT    128
#define BM    56
#define NTHR  512
#define PW    52          // 32-bit words per state row (k 0..95 as fp16 pairs + pad)
#define PG    74          // gates scratch pitch (floats)
#define PH    65          // final-h pitch (floats)

#define SCR_F     3328                  // after 64*PW state words
#define BIAS_F    (SCR_F + 256*PG)      // 22272
#define HFIN_F    (BIAS_F + 256)        // 22528
#define SMEM_FLOATS (HFIN_F + 64*PH)    // 26688
#define SMEM_BYTES  (SMEM_FLOATS*4)

__device__ __forceinline__ uint32_t packh2(float lo, float hi) {
    __half2 p = __halves2half2(__float2half_rn(lo), __float2half_rn(hi));
    return *reinterpret_cast<uint32_t*>(&p);
}

__device__ __forceinline__ void mma16(float d[4], const uint32_t a[4],
                                      uint32_t b0, uint32_t b1) {
    asm volatile(
        "mma.sync.aligned.m16n8k16.row.col.f32.f16.f16.f32 "
        "{%0,%1,%2,%3}, {%4,%5,%6,%7}, {%8,%9}, {%0,%1,%2,%3};"
        : "+f"(d[0]), "+f"(d[1]), "+f"(d[2]), "+f"(d[3])
        : "r"(a[0]), "r"(a[1]), "r"(a[2]), "r"(a[3]), "r"(b0), "r"(b1));
}

__device__ __forceinline__ float tanha(float v) {
    float r; asm("tanh.approx.f32 %0, %1;" : "=f"(r) : "f"(v)); return r;
}
__device__ __forceinline__ float fsig(float v) {        // 0.5*tanh(v/2)+0.5
    return fmaf(tanha(0.5f * v), 0.5f, 0.5f);
}

// GEMM A element: A[row=unit*4+gate][k]  (k<32: W_ih, else W_hh)
__device__ __forceinline__ float wval(const float* __restrict__ W_ih,
                                      const float* __restrict__ W_hh,
                                      int row, int k) {
    int u = row >> 2, g = row & 3;
    return (k < 32) ? W_ih[(g * 64 + u) * 32 + k]
                    : W_hh[(g * 64 + u) * 64 + (k - 32)];
}

__global__ void __launch_bounds__(NTHR, 1)
lstm_mma(const float* __restrict__ x,
         const float* __restrict__ W_ih,
         const float* __restrict__ W_hh,
         const float* __restrict__ b_ih,
         const float* __restrict__ b_hh,
         const float* __restrict__ W_fc,
         const float* __restrict__ b_fc,
         float* __restrict__ out,
         int Btotal)
{
    extern __shared__ float sm[];
    uint32_t* stw = (uint32_t*)sm;       // state[batch][k-pair]: k 0-31 x, 32-95 h (fp16)
    __half*   sth = (__half*)sm;
    float* scr  = sm + SCR_F;            // scr[gate_row][batch] f32
    float* bias = sm + BIAS_F;
    float* hfin = sm + HFIN_F;           // hfin[batch][unit] raw f32 h(T)

    const int tid   = threadIdx.x;
    const int w     = tid >> 5;
    const int l     = tid & 31;
    const int bbase = blockIdx.x * BM;

    for (int m = tid; m < 256; m += NTHR) {     // m = gate*64+unit
        int u = m & 63, g = m >> 6;
        bias[u * 4 + g] = b_ih[m] + b_hh[m];
    }
    for (int i = tid; i < 64 * PW; i += NTHR)
        stw[i] = 0u;

    // ---- warp tile: mg = w>>1 (32 gate rows), ng = w&1 (32 batch cols) ----
    const int mg = w >> 1;
    const int ng = w & 1;
    const int fr = l >> 2;              // 0..7
    const int fc = l & 3;               // 0..3

    // persistent fp16 A fragments: 2 m16-tiles x 6 k16-tiles
    uint32_t A[2][6][4];
#pragma unroll
    for (int mt = 0; mt < 2; ++mt) {
        const int r0 = 32 * mg + 16 * mt + fr;
#pragma unroll
        for (int kt = 0; kt < 6; ++kt) {
            const int k0 = kt * 16 + fc * 2;
            A[mt][kt][0] = packh2(wval(W_ih, W_hh, r0,     k0),     wval(W_ih, W_hh, r0,     k0 + 1));
            A[mt][kt][1] = packh2(wval(W_ih, W_hh, r0 + 8, k0),     wval(W_ih, W_hh, r0 + 8, k0 + 1));
            A[mt][kt][2] = packh2(wval(W_ih, W_hh, r0,     k0 + 8), wval(W_ih, W_hh, r0,     k0 + 9));
            A[mt][kt][3] = packh2(wval(W_ih, W_hh, r0 + 8, k0 + 8), wval(W_ih, W_hh, r0 + 8, k0 + 9));
        }
    }

    // ---- x staging (448 threads): batch lb, features iv..iv+3 ----
    const int lb  = tid >> 3;
    const int iv  = (tid & 7) * 4;
    const bool xth  = (tid < 448);
    const bool bval = xth && (bbase + lb) < Btotal;
    const float* xrow = x + (bval ? (size_t)(bbase + lb) * TT * 32 : 0) + iv;

    float4 xr;
    if (xth) {
        float4 x0 = *(const float4*)xrow;
        stw[lb * PW + (iv >> 1)]     = packh2(x0.x, x0.y);
        stw[lb * PW + (iv >> 1) + 1] = packh2(x0.z, x0.w);
        xr = *(const float4*)(xrow + 32);
    }
    __syncthreads();

    // ---- activation mapping: thread = (unit au, 7 batches ab..ab+6) ----
    const int au = tid >> 3;
    const int ab = (tid & 7) * 7;
    const float4 bz = *(const float4*)&bias[au * 4];
    float cst[7];
#pragma unroll
    for (int i = 0; i < 7; ++i) cst[i] = 0.0f;

    for (int t = 0; t < TT; ++t) {
        // ===== GEMM: D[32 gate rows of mg][32 batch of ng] =====
#pragma unroll
        for (int ntp = 0; ntp < 4; ++ntp) {
            const int n0 = 32 * ng + 8 * ntp;
            const uint32_t* s0 = stw + (n0 + fr) * PW + fc;
            float d0[4] = {0.f, 0.f, 0.f, 0.f};
            float d1[4] = {0.f, 0.f, 0.f, 0.f};
#pragma unroll
            for (int kt = 0; kt < 6; ++kt) {
                uint32_t b0 = s0[kt * 8];
                uint32_t b1 = s0[kt * 8 + 4];
                mma16(d0, A[0][kt], b0, b1);
                mma16(d1, A[1][kt], b0, b1);
            }
            const int r0 = 32 * mg + fr;
            const int c0 = n0 + 2 * fc;
            *(float2*)&scr[r0 * PG + c0]            = make_float2(d0[0], d0[1]);
            *(float2*)&scr[(r0 + 8) * PG + c0]      = make_float2(d0[2], d0[3]);
            *(float2*)&scr[(r0 + 16) * PG + c0]     = make_float2(d1[0], d1[1]);
            *(float2*)&scr[(r0 + 24) * PG + c0]     = make_float2(d1[2], d1[3]);
        }
        __syncthreads();

        // ===== activations (tanh.approx) =====
        const bool lastt = (t == TT - 1);
        const float* g0 = scr + (au * 4 + 0) * PG + ab;
        const float* g1 = scr + (au * 4 + 1) * PG + ab;
        const float* g2 = scr + (au * 4 + 2) * PG + ab;
        const float* g3 = scr + (au * 4 + 3) * PG + ab;
#pragma unroll
        for (int i = 0; i < 7; ++i) {
            float gi = fsig(g0[i] + bz.x);
            float gf = fsig(g1[i] + bz.y);
            float gg = tanha(g2[i] + bz.z);
            float go = fsig(g3[i] + bz.w);
            float cn = fmaf(gf, cst[i], gi * gg);
            cst[i] = cn;
            float h = go * tanha(cn);
            if (lastt) hfin[(ab + i) * PH + au] = h;
            else       sth[(ab + i) * (2 * PW) + 32 + au] = __float2half_rn(h);
        }

        if (xth && t + 1 < TT) {
            stw[lb * PW + (iv >> 1)]     = packh2(xr.x, xr.y);
            stw[lb * PW + (iv >> 1) + 1] = packh2(xr.z, xr.w);
            int tn = (t + 2 < TT) ? (t + 2) : (TT - 1);
            xr = *(const float4*)(xrow + (size_t)tn * 32);
        }
        __syncthreads();
    }

    // ---- final FC on raw f32 h(T) ----
    if (xth) {
        const int ob = tid >> 3, oo = tid & 7;
        if ((bbase + ob) < Btotal) {
            const float* hv = hfin + ob * PH;
            float a = b_fc[oo];
#pragma unroll 8
            for (int k = 0; k < 64; ++k)
                a = fmaf(hv[k], W_fc[oo * 64 + k], a);
            out[(size_t)(bbase + ob) * 8 + oo] = a;
        }
    }
}

extern "C" void kernel_launch(void* const* d_in, const int* in_sizes, int n_in,
                              void* d_out, int out_size) {
    const float* x    = (const float*)d_in[0];
    const float* W_ih = (const float*)d_in[1];
    const float* W_hh = (const float*)d_in[2];
    const float* b_ih = (const float*)d_in[3];
    const float* b_hh = (const float*)d_in[4];
    const float* W_fc = (const float*)d_in[5];
    const float* b_fc = (const float*)d_in[6];
    float* out = (float*)d_out;

    const int B = in_sizes[0] / (TT * 32);    // 8192
    const int grid = (B + BM - 1) / BM;       // 147

    cudaFuncSetAttribute(lstm_mma,
                         cudaFuncAttributeMaxDynamicSharedMemorySize,
                         SMEM_BYTES);
    lstm_mma<<<grid, NTHR, SMEM_BYTES>>>(x, W_ih, W_hh, b_ih, b_hh,
                                         W_fc, b_fc, out, B);
}

// round 10
// speedup vs baseline: 5.3119x; 1.0630x over previous
#include <cuda_runtime.h>
#include <cuda_fp16.h>
#include <cstdint>

#define TT    128
#define BM    56
#define NTHR  512
#define PW    52          // 32-bit words per state row (k 0..95 fp16 + pad)
#define PH    65          // final-h pitch (floats)

#define BIAS_F    3328                  // after 64*PW state words
#define HFIN_F    (BIAS_F + 256)
#define SMEM_FLOATS (HFIN_F + 64*PH)
#define SMEM_BYTES  (SMEM_FLOATS*4)

__device__ __forceinline__ uint32_t packh2(float lo, float hi) {
    __half2 p = __halves2half2(__float2half_rn(lo), __float2half_rn(hi));
    return *reinterpret_cast<uint32_t*>(&p);
}

__device__ __forceinline__ void mma16(float d[4], const uint32_t a[4],
                                      uint32_t b0, uint32_t b1) {
    asm volatile(
        "mma.sync.aligned.m16n8k16.row.col.f32.f16.f16.f32 "
        "{%0,%1,%2,%3}, {%4,%5,%6,%7}, {%8,%9}, {%0,%1,%2,%3};"
        : "+f"(d[0]), "+f"(d[1]), "+f"(d[2]), "+f"(d[3])
        : "r"(a[0]), "r"(a[1]), "r"(a[2]), "r"(a[3]), "r"(b0), "r"(b1));
}

__device__ __forceinline__ float tanha(float v) {
    float r; asm("tanh.approx.f32 %0, %1;" : "=f"(r) : "f"(v)); return r;
}
// sigmoid with the 0.5 input scale pre-folded into weights/bias:
__device__ __forceinline__ float fsigp(float half_v) {
    return fmaf(tanha(half_v), 0.5f, 0.5f);
}

// raw weight element: gate g, unit u, feature k (k<32: W_ih, else W_hh)
__device__ __forceinline__ float wval(const float* __restrict__ W_ih,
                                      const float* __restrict__ W_hh,
                                      int g, int u, int k) {
    return (k < 32) ? W_ih[(g * 64 + u) * 32 + k]
                    : W_hh[(g * 64 + u) * 64 + (k - 32)];
}

__global__ void __launch_bounds__(NTHR, 1)
lstm_mma(const float* __restrict__ x,
         const float* __restrict__ W_ih,
         const float* __restrict__ W_hh,
         const float* __restrict__ b_ih,
         const float* __restrict__ b_hh,
         const float* __restrict__ W_fc,
         const float* __restrict__ b_fc,
         float* __restrict__ out,
         int Btotal)
{
    extern __shared__ float sm[];
    uint32_t* stw = (uint32_t*)sm;       // state[batch][k-pair]: k 0-31 x, 32-95 h (fp16)
    __half*   sth = (__half*)sm;
    float* bias = sm + BIAS_F;           // bias[u*4+g], gates i/f/o pre-scaled by 0.5
    float* hfin = sm + HFIN_F;           // hfin[batch][unit] raw f32 h(T)

    const int tid   = threadIdx.x;
    const int w     = tid >> 5;
    const int l     = tid & 31;
    const int bbase = blockIdx.x * BM;

    for (int m = tid; m < 256; m += NTHR) {     // m = gate*64+unit
        int u = m & 63, g = m >> 6;
        float s = (g == 2) ? 1.0f : 0.5f;
        bias[u * 4 + g] = s * (b_ih[m] + b_hh[m]);
    }
    for (int i = tid; i < 64 * PW; i += NTHR)
        stw[i] = 0u;

    // ---- warp tile: mg = w>>1 (units 8mg..8mg+7), ng = w&1 (batch cols 32ng..) ----
    const int mg = w >> 1;
    const int ng = w & 1;
    const int fr = l >> 2;              // 0..7
    const int fc = l & 3;               // 0..3
    const int un = 8 * mg + fr;         // this thread's unit

    // persistent A fragments with gate->fragment-row remap:
    // tile0: rows fr -> gate i (x0.5), fr+8 -> gate f (x0.5)
    // tile1: rows fr -> gate g (x1),   fr+8 -> gate o (x0.5)
    uint32_t A[2][6][4];
#pragma unroll
    for (int mt = 0; mt < 2; ++mt) {
        const int ga = 2 * mt, gb = 2 * mt + 1;       // (0,1) then (2,3)
        const float sa = (ga == 2) ? 1.0f : 0.5f;
        const float sb = 0.5f;
#pragma unroll
        for (int kt = 0; kt < 6; ++kt) {
            const int k0 = kt * 16 + fc * 2;
            A[mt][kt][0] = packh2(sa * wval(W_ih, W_hh, ga, un, k0),
                                  sa * wval(W_ih, W_hh, ga, un, k0 + 1));
            A[mt][kt][1] = packh2(sb * wval(W_ih, W_hh, gb, un, k0),
                                  sb * wval(W_ih, W_hh, gb, un, k0 + 1));
            A[mt][kt][2] = packh2(sa * wval(W_ih, W_hh, ga, un, k0 + 8),
                                  sa * wval(W_ih, W_hh, ga, un, k0 + 9));
            A[mt][kt][3] = packh2(sb * wval(W_ih, W_hh, gb, un, k0 + 8),
                                  sb * wval(W_ih, W_hh, gb, un, k0 + 9));
        }
    }

    // ---- x staging (448 threads): batch lb, features iv..iv+3 ----
    const int lb  = tid >> 3;
    const int iv  = (tid & 7) * 4;
    const bool xth  = (tid < 448);
    const bool bval = xth && (bbase + lb) < Btotal;
    const float* xrow = x + (bval ? (size_t)(bbase + lb) * TT * 32 : 0) + iv;

    float4 xr;
    if (xth) {
        float4 x0 = *(const float4*)xrow;
        stw[lb * PW + (iv >> 1)]     = packh2(x0.x, x0.y);
        stw[lb * PW + (iv >> 1) + 1] = packh2(x0.z, x0.w);
        xr = *(const float4*)(xrow + 32);
    }
    __syncthreads();

    const float4 bz = *(const float4*)&bias[un * 4];
    float cst[8];
#pragma unroll
    for (int i = 0; i < 8; ++i) cst[i] = 0.0f;

    for (int t = 0; t < TT; ++t) {
        // ===== GEMM: this thread ends with all 4 gates of unit `un`, 8 batches =====
        float D0[4][4], D1[4][4];
#pragma unroll
        for (int ntp = 0; ntp < 4; ++ntp) {
            const int n0 = 32 * ng + 8 * ntp;
            const uint32_t* s0 = stw + (n0 + fr) * PW + fc;
#pragma unroll
            for (int q = 0; q < 4; ++q) { D0[ntp][q] = 0.f; D1[ntp][q] = 0.f; }
#pragma unroll
            for (int kt = 0; kt < 6; ++kt) {
                uint32_t b0 = s0[kt * 8];
                uint32_t b1 = s0[kt * 8 + 4];
                mma16(D0[ntp], A[0][kt], b0, b1);
                mma16(D1[ntp], A[1][kt], b0, b1);
            }
        }
        __syncthreads();   // all state reads done before h writes

        // ===== activations straight from fragments =====
        const bool lastt = (t == TT - 1);
#pragma unroll
        for (int ntp = 0; ntp < 4; ++ntp) {
#pragma unroll
            for (int e = 0; e < 2; ++e) {
                const int b = 32 * ng + 8 * ntp + 2 * fc + e;
                float gi = fsigp(D0[ntp][e]     + bz.x);
                float gf = fsigp(D0[ntp][2 + e] + bz.y);
                float gg = tanha(D1[ntp][e]     + bz.z);
                float go = fsigp(D1[ntp][2 + e] + bz.w);
                const int ci = 2 * ntp + e;
                float cn = fmaf(gf, cst[ci], gi * gg);
                cst[ci] = cn;
                float h = go * tanha(cn);
                if (lastt) hfin[b * PH + un] = h;
                else       sth[b * (2 * PW) + 32 + un] = __float2half_rn(h);
            }
        }

        if (xth && t + 1 < TT) {
            stw[lb * PW + (iv >> 1)]     = packh2(xr.x, xr.y);
            stw[lb * PW + (iv >> 1) + 1] = packh2(xr.z, xr.w);
            int tn = (t + 2 < TT) ? (t + 2) : (TT - 1);
            xr = *(const float4*)(xrow + (size_t)tn * 32);
        }
        __syncthreads();
    }

    // ---- final FC on raw f32 h(T) ----
    if (xth) {
        const int ob = tid >> 3, oo = tid & 7;
        if ((bbase + ob) < Btotal) {
            const float* hv = hfin + ob * PH;
            float a = b_fc[oo];
#pragma unroll 8
            for (int k = 0; k < 64; ++k)
                a = fmaf(hv[k], W_fc[oo * 64 + k], a);
            out[(size_t)(bbase + ob) * 8 + oo] = a;
        }
    }
}

extern "C" void kernel_launch(void* const* d_in, const int* in_sizes, int n_in,
                              void* d_out, int out_size) {
    const float* x    = (const float*)d_in[0];
    const float* W_ih = (const float*)d_in[1];
    const float* W_hh = (const float*)d_in[2];
    const float* b_ih = (const float*)d_in[3];
    const float* b_hh = (const float*)d_in[4];
    const float* W_fc = (const float*)d_in[5];
    const float* b_fc = (const float*)d_in[6];
    float* out = (float*)d_out;

    const int B = in_sizes[0] / (TT * 32);    // 8192
    const int grid = (B + BM - 1) / BM;       // 147

    cudaFuncSetAttribute(lstm_mma,
                         cudaFuncAttributeMaxDynamicSharedMemorySize,
                         SMEM_BYTES);
    lstm_mma<<<grid, NTHR, SMEM_BYTES>>>(x, W_ih, W_hh, b_ih, b_hh,
                                         W_fc, b_fc, out, B);
}

// round 11
// speedup vs baseline: 6.3243x; 1.1906x over previous
#include <cuda_runtime.h>
#include <cuda_fp16.h>
#include <cstdint>

#define TT    128
#define BM    28          // valid batches per CTA (padded to 32 in the GEMM)
#define NTHR  256
#define PW    52          // 32-bit words per state row (k 0..95 fp16 + pad)
#define PH    65          // final-h pitch (floats)

#define STB       (32*PW)               // words per state buffer
#define BIAS_F    (2*STB)               // after both state buffers (3328 words)
#define HFIN_F    (BIAS_F + 256)
#define SMEM_FLOATS (HFIN_F + 32*PH)
#define SMEM_BYTES  (SMEM_FLOATS*4)

__device__ __forceinline__ uint32_t packh2(float lo, float hi) {
    __half2 p = __halves2half2(__float2half_rn(lo), __float2half_rn(hi));
    return *reinterpret_cast<uint32_t*>(&p);
}

__device__ __forceinline__ void mma16(float d[4], const uint32_t a[4],
                                      uint32_t b0, uint32_t b1) {
    asm volatile(
        "mma.sync.aligned.m16n8k16.row.col.f32.f16.f16.f32 "
        "{%0,%1,%2,%3}, {%4,%5,%6,%7}, {%8,%9}, {%0,%1,%2,%3};"
        : "+f"(d[0]), "+f"(d[1]), "+f"(d[2]), "+f"(d[3])
        : "r"(a[0]), "r"(a[1]), "r"(a[2]), "r"(a[3]), "r"(b0), "r"(b1));
}

__device__ __forceinline__ float tanha(float v) {
    float r; asm("tanh.approx.f32 %0, %1;" : "=f"(r) : "f"(v)); return r;
}
// sigmoid with the 0.5 input scale pre-folded into weights/bias
__device__ __forceinline__ float fsigp(float half_v) {
    return fmaf(tanha(half_v), 0.5f, 0.5f);
}

// raw weight element: gate g, unit u, feature k (k<32: W_ih, else W_hh)
__device__ __forceinline__ float wval(const float* __restrict__ W_ih,
                                      const float* __restrict__ W_hh,
                                      int g, int u, int k) {
    return (k < 32) ? W_ih[(g * 64 + u) * 32 + k]
                    : W_hh[(g * 64 + u) * 64 + (k - 32)];
}

__global__ void __launch_bounds__(NTHR, 2)
lstm_mma(const float* __restrict__ x,
         const float* __restrict__ W_ih,
         const float* __restrict__ W_hh,
         const float* __restrict__ b_ih,
         const float* __restrict__ b_hh,
         const float* __restrict__ W_fc,
         const float* __restrict__ b_fc,
         float* __restrict__ out,
         int Btotal)
{
    extern __shared__ float sm[];
    uint32_t* stw = (uint32_t*)sm;       // 2 x state[32][PW]: k 0-31 x, 32-95 h (fp16)
    __half*   sth = (__half*)sm;
    float* bias = sm + BIAS_F;           // bias[u*4+g], gates i/f/o pre-scaled by 0.5
    float* hfin = sm + HFIN_F;           // hfin[batch][unit] raw f32 h(T)

    const int tid   = threadIdx.x;
    const int w     = tid >> 5;          // 0..7
    const int l     = tid & 31;
    const int bbase = blockIdx.x * BM;

    for (int m = tid; m < 256; m += NTHR) {     // m = gate*64+unit
        int u = m & 63, g = m >> 6;
        float s = (g == 2) ? 1.0f : 0.5f;
        bias[u * 4 + g] = s * (b_ih[m] + b_hh[m]);
    }
    for (int i = tid; i < 2 * STB; i += NTHR)
        stw[i] = 0u;

    // ---- warp tile: warp w owns units 8w..8w+7 (32 gate rows), all 32 batch ----
    const int fr = l >> 2;              // 0..7
    const int fc = l & 3;               // 0..3
    const int un = 8 * w + fr;          // this thread's unit

    // persistent A fragments, gate->fragment-row remap:
    // tile0: rows fr -> gate i (x0.5), fr+8 -> gate f (x0.5)
    // tile1: rows fr -> gate g (x1),   fr+8 -> gate o (x0.5)
    uint32_t A[2][6][4];
#pragma unroll
    for (int mt = 0; mt < 2; ++mt) {
        const int ga = 2 * mt, gb = 2 * mt + 1;
        const float sa = (ga == 2) ? 1.0f : 0.5f;
        const float sb = 0.5f;
#pragma unroll
        for (int kt = 0; kt < 6; ++kt) {
            const int k0 = kt * 16 + fc * 2;
            A[mt][kt][0] = packh2(sa * wval(W_ih, W_hh, ga, un, k0),
                                  sa * wval(W_ih, W_hh, ga, un, k0 + 1));
            A[mt][kt][1] = packh2(sb * wval(W_ih, W_hh, gb, un, k0),
                                  sb * wval(W_ih, W_hh, gb, un, k0 + 1));
            A[mt][kt][2] = packh2(sa * wval(W_ih, W_hh, ga, un, k0 + 8),
                                  sa * wval(W_ih, W_hh, ga, un, k0 + 9));
            A[mt][kt][3] = packh2(sb * wval(W_ih, W_hh, gb, un, k0 + 8),
                                  sb * wval(W_ih, W_hh, gb, un, k0 + 9));
        }
    }

    // ---- x staging (224 threads): batch lb (0..27), features iv..iv+3 ----
    const int lb  = tid >> 3;
    const int iv  = (tid & 7) * 4;
    const bool xth  = (tid < 224);
    const bool bval = xth && (bbase + lb) < Btotal;
    const float* xrow = x + (bval ? (size_t)(bbase + lb) * TT * 32 : 0) + iv;

    float4 xr;
    if (xth) {
        float4 x0 = *(const float4*)xrow;
        stw[lb * PW + (iv >> 1)]     = packh2(x0.x, x0.y);      // buf 0
        stw[lb * PW + (iv >> 1) + 1] = packh2(x0.z, x0.w);
        xr = *(const float4*)(xrow + 32);
    }
    __syncthreads();

    const float4 bz = *(const float4*)&bias[un * 4];
    float cst[8];
#pragma unroll
    for (int i = 0; i < 8; ++i) cst[i] = 0.0f;

    int p = 0;
    for (int t = 0; t < TT; ++t) {
        const uint32_t* sb = stw + p * STB;
        const int q = 1 - p;

        // ===== GEMM: all 4 gates of unit `un`, 8 batches, from buf p =====
        float D0[4][4], D1[4][4];
#pragma unroll
        for (int ntp = 0; ntp < 4; ++ntp) {
            const int n0 = 8 * ntp;
            const uint32_t* s0 = sb + (n0 + fr) * PW + fc;
#pragma unroll
            for (int e = 0; e < 4; ++e) { D0[ntp][e] = 0.f; D1[ntp][e] = 0.f; }
#pragma unroll
            for (int kt = 0; kt < 6; ++kt) {
                uint32_t b0 = s0[kt * 8];
                uint32_t b1 = s0[kt * 8 + 4];
                mma16(D0[ntp], A[0][kt], b0, b1);
                mma16(D1[ntp], A[1][kt], b0, b1);
            }
        }

        // ===== activations straight from fragments; h -> buf q =====
        const bool lastt = (t == TT - 1);
#pragma unroll
        for (int ntp = 0; ntp < 4; ++ntp) {
#pragma unroll
            for (int e = 0; e < 2; ++e) {
                const int b = 8 * ntp + 2 * fc + e;
                float gi = fsigp(D0[ntp][e]     + bz.x);
                float gf = fsigp(D0[ntp][2 + e] + bz.y);
                float gg = tanha(D1[ntp][e]     + bz.z);
                float go = fsigp(D1[ntp][2 + e] + bz.w);
                const int ci = 2 * ntp + e;
                float cn = fmaf(gf, cst[ci], gi * gg);
                cst[ci] = cn;
                float h = go * tanha(cn);
                if (lastt) hfin[b * PH + un] = h;
                else       sth[q * (2 * STB) + b * (2 * PW) + 32 + un] = __float2half_rn(h);
            }
        }

        // stage x(t+1) into buf q
        if (xth && t + 1 < TT) {
            stw[q * STB + lb * PW + (iv >> 1)]     = packh2(xr.x, xr.y);
            stw[q * STB + lb * PW + (iv >> 1) + 1] = packh2(xr.z, xr.w);
            int tn = (t + 2 < TT) ? (t + 2) : (TT - 1);
            xr = *(const float4*)(xrow + (size_t)tn * 32);
        }
        __syncthreads();
        p = q;
    }

    // ---- final FC on raw f32 h(T) ----
    if (xth) {
        const int ob = tid >> 3, oo = tid & 7;
        if ((bbase + ob) < Btotal) {
            const float* hv = hfin + ob * PH;
            float a = b_fc[oo];
#pragma unroll 8
            for (int k = 0; k < 64; ++k)
                a = fmaf(hv[k], W_fc[oo * 64 + k], a);
            out[(size_t)(bbase + ob) * 8 + oo] = a;
        }
    }
}

extern "C" void kernel_launch(void* const* d_in, const int* in_sizes, int n_in,
                              void* d_out, int out_size) {
    const float* x    = (const float*)d_in[0];
    const float* W_ih = (const float*)d_in[1];
    const float* W_hh = (const float*)d_in[2];
    const float* b_ih = (const float*)d_in[3];
    const float* b_hh = (const float*)d_in[4];
    const float* W_fc = (const float*)d_in[5];
    const float* b_fc = (const float*)d_in[6];
    float* out = (float*)d_out;

    const int B = in_sizes[0] / (TT * 32);    // 8192
    const int grid = (B + BM - 1) / BM;       // 293

    cudaFuncSetAttribute(lstm_mma,
                         cudaFuncAttributeMaxDynamicSharedMemorySize,
                         SMEM_BYTES);
    lstm_mma<<<grid, NTHR, SMEM_BYTES>>>(x, W_ih, W_hh, b_ih, b_hh,
                                         W_fc, b_fc, out, B);
}